// round 5
// baseline (speedup 1.0000x reference)
#include <cuda_runtime.h>

#define NN 50000
#define NE 800000
#define IND 128
#define HID 256

// ---------------- scratch (device globals; no allocation allowed) ----------
__device__ int   g_is64;
__device__ int   g_rowptr[NN + 1];
__device__ int   g_cursor[NN];
__device__ int   g_col[NE];
__device__ float g_mean[(size_t)NN * IND];   // 25.6 MB
__device__ float g_h[(size_t)NN * HID];      // 51.2 MB
__device__ float g_zl[(size_t)NN * 8];
__device__ float g_zr[(size_t)NN * 8];

__device__ __forceinline__ int edge_at(const void* ei, int is64, long long idx) {
    return is64 ? (int)((const long long*)ei)[idx] : ((const int*)ei)[idx];
}

// ---------------- edge dtype detection ----------------
__global__ void k_detect(const void* ei) {
    if (threadIdx.x == 0) {
        const unsigned int* w = (const unsigned int*)ei;
        int is64 = 1;
        #pragma unroll
        for (int i = 0; i < 8; i++)
            if (w[2 * i + 1] != 0u) is64 = 0;
        g_is64 = is64;
    }
}

// ---------------- CSR build ----------------
__global__ void k_zero_rowptr() {
    int i = blockIdx.x * blockDim.x + threadIdx.x;
    if (i <= NN) g_rowptr[i] = 0;
}

__global__ void k_count(const void* ei) {
    int t = blockIdx.x * blockDim.x + threadIdx.x;
    if (t >= NE) return;
    int is64 = g_is64;
    int dst = edge_at(ei, is64, (long long)NE + t);
    atomicAdd(&g_rowptr[dst + 1], 1);
}

// single-block inclusive scan over g_rowptr[0..NN]
__global__ void k_scan() {
    __shared__ int warpsum[32];
    __shared__ int s_carry;
    int tid = threadIdx.x, lane = tid & 31, wid = tid >> 5;
    if (tid == 0) s_carry = 0;
    __syncthreads();
    for (int base = 0; base < NN + 1; base += 1024) {
        int i = base + tid;
        int v = (i < NN + 1) ? g_rowptr[i] : 0;
        int sv = v;
        #pragma unroll
        for (int off = 1; off < 32; off <<= 1) {
            int t2 = __shfl_up_sync(0xffffffffu, sv, off);
            if (lane >= off) sv += t2;
        }
        if (lane == 31) warpsum[wid] = sv;
        __syncthreads();
        if (wid == 0) {
            int w = warpsum[lane];
            #pragma unroll
            for (int off = 1; off < 32; off <<= 1) {
                int t2 = __shfl_up_sync(0xffffffffu, w, off);
                if (lane >= off) w += t2;
            }
            warpsum[lane] = w;
        }
        __syncthreads();
        int pre = (wid > 0) ? warpsum[wid - 1] : 0;
        int incl = sv + pre + s_carry;
        if (i < NN + 1) g_rowptr[i] = incl;
        __syncthreads();
        if (tid == 1023) s_carry = incl;
        __syncthreads();
    }
}

__global__ void k_cursor() {
    int i = blockIdx.x * blockDim.x + threadIdx.x;
    if (i < NN) g_cursor[i] = g_rowptr[i];
}

__global__ void k_scatter(const void* ei) {
    int t = blockIdx.x * blockDim.x + threadIdx.x;
    if (t >= NE) return;
    int is64 = g_is64;
    int src = edge_at(ei, is64, t);
    int dst = edge_at(ei, is64, (long long)NE + t);
    int pos = atomicAdd(&g_cursor[dst], 1);
    g_col[pos] = src;
}

// ---------------- layer-1 mean aggregation (warp per node, float4 lanes) ----
__global__ void k_agg1(const float* __restrict__ x) {
    int gt = blockIdx.x * blockDim.x + threadIdx.x;
    int node = gt >> 5;
    int lane = gt & 31;
    if (node >= NN) return;
    int s = g_rowptr[node], e = g_rowptr[node + 1];
    float4 acc = make_float4(0.f, 0.f, 0.f, 0.f);
    const float4* x4 = (const float4*)x;
    for (int j = s; j < e; j++) {
        int src = g_col[j];
        float4 v = x4[(size_t)src * 32 + lane];
        acc.x += v.x; acc.y += v.y; acc.z += v.z; acc.w += v.w;
    }
    float inv = (e > s) ? 1.0f / (float)(e - s) : 0.0f;
    acc.x *= inv; acc.y *= inv; acc.z *= inv; acc.w *= inv;
    ((float4*)g_mean)[(size_t)node * 32 + lane] = acc;
}

// ---------------- layer-1 fused GEMM -----------------------------------
// h = relu( mean @ W1l^T + x @ W1r^T + b1l )   [NN x 256]
// Logical K = 256: k<128 -> (mean, W1l), k>=128 -> (x, W1r).
#define BM 128
#define BN 64
#define BK 16
__global__ __launch_bounds__(256) void k_gemm1(
    const float* __restrict__ x,
    const float* __restrict__ W1l,
    const float* __restrict__ b1l,
    const float* __restrict__ W1r)
{
    __shared__ float As[BK][BM];
    __shared__ float Bs[BK][BN];
    int t = threadIdx.x;
    int m0 = blockIdx.x * BM, n0 = blockIdx.y * BN;
    int tx = t & 15, ty = t >> 4;

    float acc[8][4];
    #pragma unroll
    for (int i = 0; i < 8; i++)
        #pragma unroll
        for (int j = 0; j < 4; j++) acc[i][j] = 0.f;

    for (int kt = 0; kt < 256; kt += BK) {
        const float* A = (kt < 128) ? g_mean : x;
        const float* W = (kt < 128) ? W1l : W1r;
        int ko = kt & 127;

        // A tile: 128x16, 2 float4 loads per thread (transposed into smem)
        #pragma unroll
        for (int r = 0; r < 2; r++) {
            int l = t + r * 256;         // 0..511
            int m = l >> 2, kq = l & 3;
            int mi = m0 + m; if (mi >= NN) mi = NN - 1;
            float4 v = *(const float4*)&A[(size_t)mi * 128 + ko + kq * 4];
            As[kq * 4 + 0][m] = v.x;
            As[kq * 4 + 1][m] = v.y;
            As[kq * 4 + 2][m] = v.z;
            As[kq * 4 + 3][m] = v.w;
        }
        // B tile: Bs[k][n] = W[n0+n][ko+k], 1 float4 per thread
        {
            int n = t >> 2, kq = t & 3;
            float4 v = *(const float4*)&W[(size_t)(n0 + n) * 128 + ko + kq * 4];
            Bs[kq * 4 + 0][n] = v.x;
            Bs[kq * 4 + 1][n] = v.y;
            Bs[kq * 4 + 2][n] = v.z;
            Bs[kq * 4 + 3][n] = v.w;
        }
        __syncthreads();

        #pragma unroll
        for (int k = 0; k < BK; k++) {
            float4 a0 = *(const float4*)&As[k][ty * 4];
            float4 a1 = *(const float4*)&As[k][ty * 4 + 64];
            float4 bb = *(const float4*)&Bs[k][tx * 4];
            float a[8] = {a0.x, a0.y, a0.z, a0.w, a1.x, a1.y, a1.z, a1.w};
            float b[4] = {bb.x, bb.y, bb.z, bb.w};
            #pragma unroll
            for (int i = 0; i < 8; i++)
                #pragma unroll
                for (int j = 0; j < 4; j++)
                    acc[i][j] += a[i] * b[j];
        }
        __syncthreads();
    }

    float4 bias = *(const float4*)&b1l[n0 + tx * 4];
    float bv[4] = {bias.x, bias.y, bias.z, bias.w};
    #pragma unroll
    for (int i = 0; i < 8; i++) {
        int m = m0 + ty * 4 + (i & 3) + (i >> 2) * 64;
        if (m < NN) {
            float4 o;
            o.x = fmaxf(acc[i][0] + bv[0], 0.f);
            o.y = fmaxf(acc[i][1] + bv[1], 0.f);
            o.z = fmaxf(acc[i][2] + bv[2], 0.f);
            o.w = fmaxf(acc[i][3] + bv[3], 0.f);
            *(float4*)&g_h[(size_t)m * 256 + n0 + tx * 4] = o;
        }
    }
}

// ---------------- layer-2 linear maps (warp per node) ----------------------
// zl = h @ W2l^T ; zr = h @ W2r^T   (5 outputs each)
__global__ __launch_bounds__(256) void k_layer2(
    const float* __restrict__ W2l, const float* __restrict__ W2r)
{
    __shared__ float sWl[5 * 256];
    __shared__ float sWr[5 * 256];
    int t = threadIdx.x;
    for (int i = t; i < 1280; i += 256) { sWl[i] = W2l[i]; sWr[i] = W2r[i]; }
    __syncthreads();

    int lane = t & 31, w = t >> 5;
    int node = blockIdx.x * 8 + w;
    if (node >= NN) return;

    float4 h0 = *(const float4*)&g_h[(size_t)node * 256 + lane * 8];
    float4 h1 = *(const float4*)&g_h[(size_t)node * 256 + lane * 8 + 4];

    float rl[5], rr[5];
    #pragma unroll
    for (int c = 0; c < 5; c++) {
        float4 wl0 = *(const float4*)&sWl[c * 256 + lane * 8];
        float4 wl1 = *(const float4*)&sWl[c * 256 + lane * 8 + 4];
        float4 wr0 = *(const float4*)&sWr[c * 256 + lane * 8];
        float4 wr1 = *(const float4*)&sWr[c * 256 + lane * 8 + 4];
        rl[c] = h0.x * wl0.x + h0.y * wl0.y + h0.z * wl0.z + h0.w * wl0.w
              + h1.x * wl1.x + h1.y * wl1.y + h1.z * wl1.z + h1.w * wl1.w;
        rr[c] = h0.x * wr0.x + h0.y * wr0.y + h0.z * wr0.z + h0.w * wr0.w
              + h1.x * wr1.x + h1.y * wr1.y + h1.z * wr1.z + h1.w * wr1.w;
    }
    #pragma unroll
    for (int c = 0; c < 5; c++) {
        #pragma unroll
        for (int off = 16; off; off >>= 1) {
            rl[c] += __shfl_xor_sync(0xffffffffu, rl[c], off);
            rr[c] += __shfl_xor_sync(0xffffffffu, rr[c], off);
        }
    }
    if (lane == 0) {
        #pragma unroll
        for (int c = 0; c < 5; c++) {
            g_zl[(size_t)node * 8 + c] = rl[c];
            g_zr[(size_t)node * 8 + c] = rr[c];
        }
    }
}

// ---------------- layer-2 aggregation + epilogue (warp per node) -----------
__global__ void k_out(const float* __restrict__ b2l, float* __restrict__ out) {
    int gt = blockIdx.x * blockDim.x + threadIdx.x;
    int node = gt >> 5;
    int lane = gt & 31;
    if (node >= NN) return;
    int s = g_rowptr[node], e = g_rowptr[node + 1];
    float a[5] = {0.f, 0.f, 0.f, 0.f, 0.f};
    for (int j = s + lane; j < e; j += 32) {
        int src = g_col[j];
        float4 z0 = *(const float4*)&g_zl[(size_t)src * 8];
        float z4 = g_zl[(size_t)src * 8 + 4];
        a[0] += z0.x; a[1] += z0.y; a[2] += z0.z; a[3] += z0.w; a[4] += z4;
    }
    #pragma unroll
    for (int c = 0; c < 5; c++)
        #pragma unroll
        for (int off = 16; off; off >>= 1)
            a[c] += __shfl_xor_sync(0xffffffffu, a[c], off);
    if (lane == 0) {
        float inv = (e > s) ? 1.0f / (float)(e - s) : 0.0f;
        #pragma unroll
        for (int c = 0; c < 5; c++) {
            float v = a[c] * inv + b2l[c] + g_zr[(size_t)node * 8 + c];
            out[(size_t)node * 5 + c] = fmaxf(v, 0.f);
        }
    }
}

// ---------------- launcher ----------------
extern "C" void kernel_launch(void* const* d_in, const int* in_sizes, int n_in,
                              void* d_out, int out_size) {
    const float* x   = (const float*)d_in[0];
    const void*  ei  = d_in[1];
    const float* W1l = (const float*)d_in[2];
    const float* b1l = (const float*)d_in[3];
    const float* W1r = (const float*)d_in[4];
    const float* W2l = (const float*)d_in[5];
    const float* b2l = (const float*)d_in[6];
    const float* W2r = (const float*)d_in[7];
    float* out = (float*)d_out;

    k_detect<<<1, 32>>>(ei);
    k_zero_rowptr<<<(NN + 1 + 255) / 256, 256>>>();
    k_count<<<(NE + 255) / 256, 256>>>(ei);
    k_scan<<<1, 1024>>>();
    k_cursor<<<(NN + 255) / 256, 256>>>();
    k_scatter<<<(NE + 255) / 256, 256>>>(ei);

    k_agg1<<<(NN * 32 + 255) / 256, 256>>>(x);

    dim3 g1((NN + BM - 1) / BM, HID / BN);
    k_gemm1<<<g1, 256>>>(x, W1l, b1l, W1r);

    k_layer2<<<(NN + 7) / 8, 256>>>(W2l, W2r);
    k_out<<<(NN * 32 + 255) / 256, 256>>>(b2l, out);
}

// round 6
// speedup vs baseline: 1.0020x; 1.0020x over previous
#include <cuda_runtime.h>

#define NN 50000
#define NE 800000
#define IND 128
#define HID 256

// ---------------- scratch (device globals; no allocation allowed) ----------
__device__ int   g_is64;
__device__ int   g_rowptr[NN + 1];
__device__ int   g_cursor[NN];
__device__ int   g_col[NE];
__device__ float g_mean[(size_t)NN * IND];   // 25.6 MB
__device__ float g_h[(size_t)NN * HID];      // 51.2 MB
__device__ float g_zl[(size_t)NN * 8];
__device__ float g_zr[(size_t)NN * 8];

__device__ __forceinline__ int edge_at(const void* ei, int is64, long long idx) {
    return is64 ? (int)((const long long*)ei)[idx] : ((const int*)ei)[idx];
}

// ---------------- edge dtype detection ----------------
__global__ void k_detect(const void* ei) {
    if (threadIdx.x == 0) {
        const unsigned int* w = (const unsigned int*)ei;
        int is64 = 1;
        #pragma unroll
        for (int i = 0; i < 8; i++)
            if (w[2 * i + 1] != 0u) is64 = 0;
        g_is64 = is64;
    }
}

// ---------------- CSR build ----------------
__global__ void k_zero_rowptr() {
    int i = blockIdx.x * blockDim.x + threadIdx.x;
    if (i <= NN) g_rowptr[i] = 0;
}

__global__ void k_count(const void* ei) {
    int t = blockIdx.x * blockDim.x + threadIdx.x;
    if (t >= NE) return;
    int is64 = g_is64;
    int dst = edge_at(ei, is64, (long long)NE + t);
    atomicAdd(&g_rowptr[dst + 1], 1);
}

// single-block inclusive scan over g_rowptr[0..NN]
__global__ void k_scan() {
    __shared__ int warpsum[32];
    __shared__ int s_carry;
    int tid = threadIdx.x, lane = tid & 31, wid = tid >> 5;
    if (tid == 0) s_carry = 0;
    __syncthreads();
    for (int base = 0; base < NN + 1; base += 1024) {
        int i = base + tid;
        int v = (i < NN + 1) ? g_rowptr[i] : 0;
        int sv = v;
        #pragma unroll
        for (int off = 1; off < 32; off <<= 1) {
            int t2 = __shfl_up_sync(0xffffffffu, sv, off);
            if (lane >= off) sv += t2;
        }
        if (lane == 31) warpsum[wid] = sv;
        __syncthreads();
        if (wid == 0) {
            int w = warpsum[lane];
            #pragma unroll
            for (int off = 1; off < 32; off <<= 1) {
                int t2 = __shfl_up_sync(0xffffffffu, w, off);
                if (lane >= off) w += t2;
            }
            warpsum[lane] = w;
        }
        __syncthreads();
        int pre = (wid > 0) ? warpsum[wid - 1] : 0;
        int incl = sv + pre + s_carry;
        if (i < NN + 1) g_rowptr[i] = incl;
        __syncthreads();
        if (tid == 1023) s_carry = incl;
        __syncthreads();
    }
}

__global__ void k_cursor() {
    int i = blockIdx.x * blockDim.x + threadIdx.x;
    if (i < NN) g_cursor[i] = g_rowptr[i];
}

__global__ void k_scatter(const void* ei) {
    int t = blockIdx.x * blockDim.x + threadIdx.x;
    if (t >= NE) return;
    int is64 = g_is64;
    int src = edge_at(ei, is64, t);
    int dst = edge_at(ei, is64, (long long)NE + t);
    int pos = atomicAdd(&g_cursor[dst], 1);
    g_col[pos] = src;
}

// ---------------- layer-1 mean aggregation (warp per node, float4 lanes) ----
__global__ void k_agg1(const float* __restrict__ x) {
    int gt = blockIdx.x * blockDim.x + threadIdx.x;
    int node = gt >> 5;
    int lane = gt & 31;
    if (node >= NN) return;
    int s = g_rowptr[node], e = g_rowptr[node + 1];
    float4 acc = make_float4(0.f, 0.f, 0.f, 0.f);
    const float4* x4 = (const float4*)x;
    for (int j = s; j < e; j++) {
        int src = g_col[j];
        float4 v = x4[(size_t)src * 32 + lane];
        acc.x += v.x; acc.y += v.y; acc.z += v.z; acc.w += v.w;
    }
    float inv = (e > s) ? 1.0f / (float)(e - s) : 0.0f;
    acc.x *= inv; acc.y *= inv; acc.z *= inv; acc.w *= inv;
    ((float4*)g_mean)[(size_t)node * 32 + lane] = acc;
}

// ---------------- layer-1 fused GEMM -----------------------------------
// h = relu( mean @ W1l^T + x @ W1r^T + b1l )   [NN x 256]
// Logical K = 256: k<128 -> (mean, W1l), k>=128 -> (x, W1r).
#define BM 128
#define BN 64
#define BK 16
__global__ __launch_bounds__(256) void k_gemm1(
    const float* __restrict__ x,
    const float* __restrict__ W1l,
    const float* __restrict__ b1l,
    const float* __restrict__ W1r)
{
    __shared__ float As[BK][BM];
    __shared__ float Bs[BK][BN];
    int t = threadIdx.x;
    int m0 = blockIdx.x * BM, n0 = blockIdx.y * BN;
    int tx = t & 15, ty = t >> 4;

    float acc[8][4];
    #pragma unroll
    for (int i = 0; i < 8; i++)
        #pragma unroll
        for (int j = 0; j < 4; j++) acc[i][j] = 0.f;

    for (int kt = 0; kt < 256; kt += BK) {
        const float* A = (kt < 128) ? g_mean : x;
        const float* W = (kt < 128) ? W1l : W1r;
        int ko = kt & 127;

        // A tile: 128x16, 2 float4 loads per thread (transposed into smem)
        #pragma unroll
        for (int r = 0; r < 2; r++) {
            int l = t + r * 256;         // 0..511
            int m = l >> 2, kq = l & 3;
            int mi = m0 + m; if (mi >= NN) mi = NN - 1;
            float4 v = *(const float4*)&A[(size_t)mi * 128 + ko + kq * 4];
            As[kq * 4 + 0][m] = v.x;
            As[kq * 4 + 1][m] = v.y;
            As[kq * 4 + 2][m] = v.z;
            As[kq * 4 + 3][m] = v.w;
        }
        // B tile: Bs[k][n] = W[n0+n][ko+k], 1 float4 per thread
        {
            int n = t >> 2, kq = t & 3;
            float4 v = *(const float4*)&W[(size_t)(n0 + n) * 128 + ko + kq * 4];
            Bs[kq * 4 + 0][n] = v.x;
            Bs[kq * 4 + 1][n] = v.y;
            Bs[kq * 4 + 2][n] = v.z;
            Bs[kq * 4 + 3][n] = v.w;
        }
        __syncthreads();

        #pragma unroll
        for (int k = 0; k < BK; k++) {
            float4 a0 = *(const float4*)&As[k][ty * 4];
            float4 a1 = *(const float4*)&As[k][ty * 4 + 64];
            float4 bb = *(const float4*)&Bs[k][tx * 4];
            float a[8] = {a0.x, a0.y, a0.z, a0.w, a1.x, a1.y, a1.z, a1.w};
            float b[4] = {bb.x, bb.y, bb.z, bb.w};
            #pragma unroll
            for (int i = 0; i < 8; i++)
                #pragma unroll
                for (int j = 0; j < 4; j++)
                    acc[i][j] += a[i] * b[j];
        }
        __syncthreads();
    }

    float4 bias = *(const float4*)&b1l[n0 + tx * 4];
    float bv[4] = {bias.x, bias.y, bias.z, bias.w};
    #pragma unroll
    for (int i = 0; i < 8; i++) {
        int m = m0 + ty * 4 + (i & 3) + (i >> 2) * 64;
        if (m < NN) {
            float4 o;
            o.x = fmaxf(acc[i][0] + bv[0], 0.f);
            o.y = fmaxf(acc[i][1] + bv[1], 0.f);
            o.z = fmaxf(acc[i][2] + bv[2], 0.f);
            o.w = fmaxf(acc[i][3] + bv[3], 0.f);
            *(float4*)&g_h[(size_t)m * 256 + n0 + tx * 4] = o;
        }
    }
}

// ---------------- layer-2 linear maps (warp per node) ----------------------
// zl = h @ W2l^T ; zr = h @ W2r^T   (5 outputs each)
__global__ __launch_bounds__(256) void k_layer2(
    const float* __restrict__ W2l, const float* __restrict__ W2r)
{
    __shared__ float sWl[5 * 256];
    __shared__ float sWr[5 * 256];
    int t = threadIdx.x;
    for (int i = t; i < 1280; i += 256) { sWl[i] = W2l[i]; sWr[i] = W2r[i]; }
    __syncthreads();

    int lane = t & 31, w = t >> 5;
    int node = blockIdx.x * 8 + w;
    if (node >= NN) return;

    float4 h0 = *(const float4*)&g_h[(size_t)node * 256 + lane * 8];
    float4 h1 = *(const float4*)&g_h[(size_t)node * 256 + lane * 8 + 4];

    float rl[5], rr[5];
    #pragma unroll
    for (int c = 0; c < 5; c++) {
        float4 wl0 = *(const float4*)&sWl[c * 256 + lane * 8];
        float4 wl1 = *(const float4*)&sWl[c * 256 + lane * 8 + 4];
        float4 wr0 = *(const float4*)&sWr[c * 256 + lane * 8];
        float4 wr1 = *(const float4*)&sWr[c * 256 + lane * 8 + 4];
        rl[c] = h0.x * wl0.x + h0.y * wl0.y + h0.z * wl0.z + h0.w * wl0.w
              + h1.x * wl1.x + h1.y * wl1.y + h1.z * wl1.z + h1.w * wl1.w;
        rr[c] = h0.x * wr0.x + h0.y * wr0.y + h0.z * wr0.z + h0.w * wr0.w
              + h1.x * wr1.x + h1.y * wr1.y + h1.z * wr1.z + h1.w * wr1.w;
    }
    #pragma unroll
    for (int c = 0; c < 5; c++) {
        #pragma unroll
        for (int off = 16; off; off >>= 1) {
            rl[c] += __shfl_xor_sync(0xffffffffu, rl[c], off);
            rr[c] += __shfl_xor_sync(0xffffffffu, rr[c], off);
        }
    }
    if (lane == 0) {
        #pragma unroll
        for (int c = 0; c < 5; c++) {
            g_zl[(size_t)node * 8 + c] = rl[c];
            g_zr[(size_t)node * 8 + c] = rr[c];
        }
    }
}

// ---------------- layer-2 aggregation + epilogue (warp per node) -----------
__global__ void k_out(const float* __restrict__ b2l, float* __restrict__ out) {
    int gt = blockIdx.x * blockDim.x + threadIdx.x;
    int node = gt >> 5;
    int lane = gt & 31;
    if (node >= NN) return;
    int s = g_rowptr[node], e = g_rowptr[node + 1];
    float a[5] = {0.f, 0.f, 0.f, 0.f, 0.f};
    for (int j = s + lane; j < e; j += 32) {
        int src = g_col[j];
        float4 z0 = *(const float4*)&g_zl[(size_t)src * 8];
        float z4 = g_zl[(size_t)src * 8 + 4];
        a[0] += z0.x; a[1] += z0.y; a[2] += z0.z; a[3] += z0.w; a[4] += z4;
    }
    #pragma unroll
    for (int c = 0; c < 5; c++)
        #pragma unroll
        for (int off = 16; off; off >>= 1)
            a[c] += __shfl_xor_sync(0xffffffffu, a[c], off);
    if (lane == 0) {
        float inv = (e > s) ? 1.0f / (float)(e - s) : 0.0f;
        #pragma unroll
        for (int c = 0; c < 5; c++) {
            float v = a[c] * inv + b2l[c] + g_zr[(size_t)node * 8 + c];
            out[(size_t)node * 5 + c] = fmaxf(v, 0.f);
        }
    }
}

// ---------------- launcher ----------------
extern "C" void kernel_launch(void* const* d_in, const int* in_sizes, int n_in,
                              void* d_out, int out_size) {
    const float* x   = (const float*)d_in[0];
    const void*  ei  = d_in[1];
    const float* W1l = (const float*)d_in[2];
    const float* b1l = (const float*)d_in[3];
    const float* W1r = (const float*)d_in[4];
    const float* W2l = (const float*)d_in[5];
    const float* b2l = (const float*)d_in[6];
    const float* W2r = (const float*)d_in[7];
    float* out = (float*)d_out;

    k_detect<<<1, 32>>>(ei);
    k_zero_rowptr<<<(NN + 1 + 255) / 256, 256>>>();
    k_count<<<(NE + 255) / 256, 256>>>(ei);
    k_scan<<<1, 1024>>>();
    k_cursor<<<(NN + 255) / 256, 256>>>();
    k_scatter<<<(NE + 255) / 256, 256>>>(ei);

    k_agg1<<<(NN * 32 + 255) / 256, 256>>>(x);

    dim3 g1((NN + BM - 1) / BM, HID / BN);
    k_gemm1<<<g1, 256>>>(x, W1l, b1l, W1r);

    k_layer2<<<(NN + 7) / 8, 256>>>(W2l, W2r);
    k_out<<<(NN * 32 + 255) / 256, 256>>>(b2l, out);
}